// round 5
// baseline (speedup 1.0000x reference)
#include <cuda_runtime.h>
#include <math.h>

#define HW    256
#define SNUM  257
#define RPT   9          // ceil(257/32) support entries per lane
#define NWARP 8
#define NTHR  (NWARP*32)
#define FULLM 0xffffffffu
#define EPSF  1e-9f
#define MINNORM 1.17549435e-38f

// --- fp32 ops with flush-to-zero, matching XLA:GPU ftz semantics ---
__device__ __forceinline__ float fmul_ftz(float a, float b) {
    float r; asm("mul.rn.ftz.f32 %0,%1,%2;" : "=f"(r) : "f"(a), "f"(b)); return r;
}
__device__ __forceinline__ float ffma_ftz(float a, float b, float c) {
    float r; asm("fma.rn.ftz.f32 %0,%1,%2,%3;" : "=f"(r) : "f"(a), "f"(b), "f"(c)); return r;
}
__device__ __forceinline__ float fadd_ftz(float a, float b) {
    float r; asm("add.rn.ftz.f32 %0,%1,%2;" : "=f"(r) : "f"(a), "f"(b)); return r;
}

__global__ __launch_bounds__(NTHR, 1) void spair_obj_kl_kernel(
    const float* __restrict__ z_pres,
    const float* __restrict__ z_prob,
    float* __restrict__ out)
{
    __shared__ float s_invd[HW];
    __shared__ float s_prob[NWARP][HW];
    __shared__ float s_c0[NWARP][HW];    // prob*log(prob+eps) + (1-prob)*log(1-prob+eps)
    __shared__ float s_samp[NWARP][HW];
    __shared__ float s_aux[NWARP][HW];   // csf trajectory, later reused for kl output

    const int tid  = threadIdx.x;
    const int lane = tid & 31;
    const int w    = tid >> 5;
    const int b    = blockIdx.x * NWARP + w;

    if (tid < HW) s_invd[tid] = 1.0f / (float)(HW - tid);

    // ---- stage inputs: 8 contiguous elements per lane (2x float4) ----
    const float4* zp4 = (const float4*)(z_pres + (size_t)b * HW);
    const float4* pb4 = (const float4*)(z_prob + (size_t)b * HW);
    float4 a0 = zp4[lane*2], a1 = zp4[lane*2+1];
    float4 p0 = pb4[lane*2], p1 = pb4[lane*2+1];

    float smp[8] = { rintf(a0.x), rintf(a0.y), rintf(a0.z), rintf(a0.w),
                     rintf(a1.x), rintf(a1.y), rintf(a1.z), rintf(a1.w) };
    float prv[8] = { p0.x, p0.y, p0.z, p0.w, p1.x, p1.y, p1.z, p1.w };

    // ---- warp-scan prefix sum of samples -> count_so_far per step ----
    float tot = 0.f;
    #pragma unroll
    for (int k = 0; k < 8; k++) tot += smp[k];
    float incl = tot;
    #pragma unroll
    for (int off = 1; off < 32; off <<= 1) {
        float o = __shfl_up_sync(FULLM, incl, off);
        if (lane >= off) incl += o;
    }
    float run = incl - tot;   // exclusive prefix at element lane*8
    #pragma unroll
    for (int k = 0; k < 8; k++) {
        int i = lane*8 + k;
        s_aux[w][i]  = run;          // csf BEFORE step i
        s_samp[w][i] = smp[k];
        run += smp[k];
        float pr = prv[k];
        s_prob[w][i] = pr;
        s_c0[w][i] = pr * __logf(pr + EPSF)
                   + (1.0f - pr) * __logf(1.0f - pr + EPSF);
    }

    // ---- initial count distribution cd0[j] ~ (1-p) p^j, normalized, FTZ ----
    float e2   = (float)exp(2.0);
    float pf   = 1.0f / (e2 + 1.0f);
    float onem = 1.0f - pf;
    double pw[9];
    pw[0] = (double)pf;
    #pragma unroll
    for (int k = 1; k < 9; k++) pw[k] = pw[k-1] * pw[k-1];

    float cd[RPT], fj[RPT];
    float wsum = 0.f;
    #pragma unroll
    for (int r = 0; r < RPT; r++) {
        int j = lane + 32 * r;
        float wv = 0.f;
        if (j < SNUM) {
            double acc = 1.0;
            int jj = j;
            #pragma unroll
            for (int k = 0; k < 9; k++) { if (jj & 1) acc *= pw[k]; jj >>= 1; }
            wv = (float)acc * onem;
            if (wv < MINNORM) wv = 0.0f;   // ftz: flush subnormal prior entries
        }
        fj[r] = (float)j;        // harmless garbage slot has cd==0
        cd[r] = wv;
        wsum += wv;
    }
    #pragma unroll
    for (int off = 16; off; off >>= 1) wsum += __shfl_xor_sync(FULLM, wsum, off);
    #pragma unroll
    for (int r = 0; r < RPT; r++) {
        float v = cd[r] / wsum;
        if (v < MINNORM) v = 0.0f;
        cd[r] = v;
    }

    __syncthreads();

    const float LEPS = __logf(EPSF);
    int die = HW;               // first dead step (p_z == 0 from here on)

    // ---- serial scan (live phase), ftz fp32 throughout ----
    #pragma unroll 1
    for (int i = 0; i < HW; i++) {
        float sA  = s_samp[w][i];
        float cs  = s_aux[w][i];
        float pr  = s_prob[w][i];
        float c0  = s_c0[w][i];
        float ivd = s_invd[i];
        float d   = (float)(HW - i);
        float s1  = 1.0f - sA;          // mult = s2*pzg + s1  (==pzg or 1-pzg exactly)
        float s2  = sA + sA - 1.0f;
        float num = 0.f, nrm = 0.f;
        #pragma unroll
        for (int r = 0; r < RPT; r++) {
            float t = fj[r] - cs;
            t = fmaxf(t, 0.0f);
            t = fminf(t, d);
            float pzg = fmul_ftz(t, ivd);        // clip(j-csf,0,d)/d
            num = ffma_ftz(cd[r], pzg, num);     // p_z uses OLD cd
            float m  = ffma_ftz(s2, pzg, s1);
            float c1 = fmul_ftz(m, cd[r]);       // ftz: decaying tail flushes like ref
            nrm = fadd_ftz(nrm, c1);
            cd[r] = c1;
        }
        #pragma unroll
        for (int off = 16; off; off >>= 1) {
            num = fadd_ftz(num, __shfl_xor_sync(FULLM, num, off));
            nrm = fadd_ftz(nrm, __shfl_xor_sync(FULLM, nrm, off));
        }
        float lpz  = __logf(num + EPSF);
        float l1pz = __logf(1.0f - num + EPSF);
        float kl = c0 - pr * lpz - (1.0f - pr) * l1pz;
        s_aux[w][i] = kl;                        // stage output (csf slot consumed)

        if (nrm == 0.0f) { die = i + 1; break; } // exact under ftz: all cd flushed to 0

        float invn = 1.0f / fmaxf(nrm, 1e-6f);
        #pragma unroll
        for (int r = 0; r < RPT; r++) cd[r] = fmul_ftz(cd[r], invn);
    }

    // ---- dead phase: p_z == 0 forever -> kl closed-form, lane-parallel ----
    for (int i = die + lane; i < HW; i += 32) {
        s_aux[w][i] = s_c0[w][i] - s_prob[w][i] * LEPS;
    }
    __syncwarp();

    // ---- coalesced float4 store ----
    float* ob = out + (size_t)b * HW;
    #pragma unroll
    for (int q = 0; q < 2; q++) {
        int base = lane*8 + q*4;
        float4 v = make_float4(s_aux[w][base], s_aux[w][base+1],
                               s_aux[w][base+2], s_aux[w][base+3]);
        ((float4*)ob)[lane*2 + q] = v;
    }
}

extern "C" void kernel_launch(void* const* d_in, const int* in_sizes, int n_in,
                              void* d_out, int out_size)
{
    const float* z_pres = (const float*)d_in[0];
    const float* z_prob = (const float*)d_in[1];
    float* out = (float*)d_out;
    int B = in_sizes[0] / HW;            // 1024
    spair_obj_kl_kernel<<<B / NWARP, NTHR>>>(z_pres, z_prob, out);
}